// round 8
// baseline (speedup 1.0000x reference)
#include <cuda_runtime.h>

#define L_FIXED 2048
#define MAXB    16
#define EPSF    1e-8f
#define GDIM    32
#define NCELL   (GDIM * GDIM * GDIM)
#define SLOTS   24
#define GMIN    (-64.0f)
#define GINV    0.25f                     // 1 / cell_size(4.0)
#define NTHREADS 256
#define NBLOCKS  128                      // <= 148 SMs: co-resident, spin-safe

// ---- static scratch (zero-initialized at module load; self-resetting) ----
__device__ int    g_cnt[MAXB][NCELL];
__device__ short  g_slot[MAXB][NCELL][SLOTS];
__device__ int    g_cellof[MAXB][L_FIXED];
__device__ double g_clash = 0.0;
__device__ double g_bn    = 0.0;
__device__ double g_bd    = 0.0;
__device__ double g_lin   = 0.0;
__device__ double g_S[MAXB];
__device__ int    g_bar_cnt[2]  = {0, 0};
__device__ int    g_bar_flag[2] = {0, 0};

__device__ __forceinline__ float warp_sum(float v) {
    #pragma unroll
    for (int off = 16; off > 0; off >>= 1)
        v += __shfl_down_sync(0xffffffffu, v, off);
    return v;
}
__device__ __forceinline__ int cell_coord(float x) {
    int c = (int)floorf((x - GMIN) * GINV);
    return min(max(c, 0), GDIM - 1);
}

// sense-reversing grid barrier: self-resets, safe across graph replays
__device__ __forceinline__ void grid_barrier(int idx) {
    __syncthreads();
    if (threadIdx.x == 0) {
        int pre = *(volatile int*)&g_bar_flag[idx];
        __threadfence();
        int old = atomicAdd(&g_bar_cnt[idx], 1);
        if (old == NBLOCKS - 1) {
            g_bar_cnt[idx] = 0;
            __threadfence();
            atomicExch(&g_bar_flag[idx], pre ^ 1);
        } else {
            while (*(volatile int*)&g_bar_flag[idx] == pre) { __nanosleep(32); }
        }
        __threadfence();
    }
    __syncthreads();
}

// ============================================================
// One launch. grid = 128 x 256 threads (32768).
// Phase A: bin atoms + bond term + mask stats.
// Phase B: cell-list neighbor search (ordered pair sum).
// Phase C: clear cell counts + block-0 finalize & reset.
// ============================================================
__global__ void __launch_bounds__(NTHREADS)
violation_kernel(const float* __restrict__ pos,
                 const float* __restrict__ mask,
                 float* __restrict__ out, int B)
{
    const int tid = threadIdx.x;
    const int t   = blockIdx.x * NTHREADS + tid;
    const int natoms = B * L_FIXED;
    __shared__ float swr[NTHREADS / 32];

    // ================= Phase A: bin + bond + stats =================
    float bn = 0.f, bd = 0.f, lin = 0.f, S = 0.f;
    if (t < natoms) {
        const int b = t >> 11;
        const int i = t & 2047;
        const float* P = pos  + (size_t)b * L_FIXED * 3;
        const float* M = mask + (size_t)b * L_FIXED;

        const float m = M[i];
        const float x = P[3*i], y = P[3*i+1], z = P[3*i+2];

        S = m; lin = m * m;
        if (i + 1 < L_FIXED) {
            float mj = M[i + 1];
            float dx = P[3*(i+1)]   - x;
            float dy = P[3*(i+1)+1] - y;
            float dz = P[3*(i+1)+2] - z;
            float d  = sqrtf(dx*dx + dy*dy + dz*dz + EPSF);
            float viol = fmaxf(fabsf(d - 3.8f) - 0.4f, 0.0f);
            float mm = m * mj;
            bd = mm;
            bn = viol * mm;
            lin += 2.0f * mm;
        }
        if (i + 2 < L_FIXED) lin += 2.0f * m * M[i + 2];

        int cid = (cell_coord(x) << 10) | (cell_coord(y) << 5) | cell_coord(z);
        g_cellof[b][i] = cid;
        if (m != 0.0f) {
            int s = atomicAdd(&g_cnt[b][cid], 1);
            if (s < SLOTS) g_slot[b][cid][s] = (short)i;
        }
    }
    // block-reduced stat atomics (blocks never straddle a batch: 256 | 2048)
    {
        float v[4] = {bn, bd, lin, S};
        #pragma unroll
        for (int k = 0; k < 4; k++) {
            float w = warp_sum(v[k]);
            if ((tid & 31) == 0) swr[tid >> 5] = w;
            __syncthreads();
            if (tid == 0) {
                float s = 0.f;
                #pragma unroll
                for (int q = 0; q < NTHREADS / 32; q++) s += swr[q];
                if (s != 0.0f) {
                    if (k == 0) atomicAdd(&g_bn, (double)s);
                    else if (k == 1) atomicAdd(&g_bd, (double)s);
                    else if (k == 2) atomicAdd(&g_lin, (double)s);
                    else atomicAdd(&g_S[t >> 11], (double)s);
                }
            }
            __syncthreads();
        }
    }

    grid_barrier(0);

    // ================= Phase B: neighbor search =================
    const int nwork = natoms * 27;
    float acc = 0.0f;
    for (int w = t; w < nwork; w += NBLOCKS * NTHREADS) {
        const unsigned a = (unsigned)w / 27u;
        const int o = w - (int)a * 27;
        const int b = (int)(a >> 11);
        const int i = (int)(a & 2047u);
        const float* P = pos  + (size_t)b * L_FIXED * 3;
        const float* M = mask + (size_t)b * L_FIXED;

        const float mi = M[i];
        if (mi != 0.0f) {
            const float xi = P[3*i], yi = P[3*i+1], zi = P[3*i+2];
            const int cid = g_cellof[b][i];
            const int nx = (cid >> 10)        + (o / 9)       - 1;
            const int ny = ((cid >> 5) & 31)  + ((o / 3) % 3) - 1;
            const int nz = (cid & 31)         + (o % 3)       - 1;
            if (((unsigned)nx < GDIM) & ((unsigned)ny < GDIM) & ((unsigned)nz < GDIM)) {
                const int ncid = (nx << 10) | (ny << 5) | nz;
                int c = g_cnt[b][ncid];
                if (c > SLOTS) c = SLOTS;
                for (int s = 0; s < c; s++) {
                    const int j = (int)g_slot[b][ncid][s];
                    const int d = j - i;
                    if (d > 2 || d < -2) {
                        float dx = xi - P[3*j];
                        float dy = yi - P[3*j+1];
                        float dz = zi - P[3*j+2];
                        float d2 = dx*dx + dy*dy + dz*dz;
                        if (d2 < 2.25f) {
                            float v = fmaxf(1.5f - sqrtf(d2 + EPSF), 0.0f);
                            acc += v * mi * M[j];
                        }
                    }
                }
            }
        }
    }
    acc = warp_sum(acc);
    if ((tid & 31) == 0) swr[tid >> 5] = acc;
    __syncthreads();
    if (tid == 0) {
        float s = 0.f;
        #pragma unroll
        for (int q = 0; q < NTHREADS / 32; q++) s += swr[q];
        if (s != 0.0f) atomicAdd(&g_clash, (double)s);
    }

    grid_barrier(1);

    // ================= Phase C: clear + finalize =================
    if (t < natoms) {
        int b = t >> 11;
        int i = t & 2047;
        g_cnt[b][g_cellof[b][i]] = 0;      // idempotent per-cell clear
    }
    if (blockIdx.x == 0 && tid == 0) {
        double pd = 0.0;
        #pragma unroll
        for (int bb = 0; bb < MAXB; bb++) {
            if (bb < B) { double Sb = g_S[bb]; pd += Sb * Sb; }
        }
        pd -= g_lin;
        double bond  = g_bn / (g_bd + 1e-8);
        double clash = g_clash / (pd + 1e-8);
        out[0] = (float)bond;
        out[1] = (float)clash;
        out[2] = (float)(bond + clash);
        g_clash = 0.0; g_bn = 0.0; g_bd = 0.0; g_lin = 0.0;
        #pragma unroll
        for (int bb = 0; bb < MAXB; bb++) g_S[bb] = 0.0;
    }
}

extern "C" void kernel_launch(void* const* d_in, const int* in_sizes, int n_in,
                              void* d_out, int out_size)
{
    const float* pos  = (const float*)d_in[0];
    const float* mask = (const float*)d_in[1];
    int B = in_sizes[1] / L_FIXED;
    if (B > MAXB) B = MAXB;

    violation_kernel<<<NBLOCKS, NTHREADS>>>(pos, mask, (float*)d_out, B);
}